// round 4
// baseline (speedup 1.0000x reference)
#include <cuda_runtime.h>
#include <math.h>
#include <stdint.h>
#include <stddef.h>

#define Bdim  64
#define Tdim  512
#define INdim 256
#define Hdim  512
#define G4    2048
#define NBLK  128
#define SHP   516   // padded pitch for h tile rows (floats)

// ---------------- device-global scratch (no allocations allowed) ----------------
__device__ __align__(16) float g_G[(size_t)Bdim * Tdim * G4];     // input-gate precompute, reused per layer
__device__ __align__(16) float g_hs0[(size_t)Bdim * Tdim * Hdim]; // layer-0 hidden sequence
__device__ __align__(16) float g_bufA[Bdim * Hdim];               // double-buffered h state
__device__ __align__(16) float g_bufB[Bdim * Hdim];
__device__ __align__(16) float g_h0f[Bdim * Hdim];                // layer-0 final h
__device__ __align__(16) float g_c0f[Bdim * Hdim];                // layer-0 final c
__device__ unsigned g_barcnt;                                     // zero-initialized
__device__ volatile unsigned g_bargen;

// ---------------- software grid barrier (all NBLK CTAs resident) ----------------
__device__ __forceinline__ void grid_barrier() {
    __syncthreads();
    if (threadIdx.x == 0) {
        unsigned gen = g_bargen;          // read BEFORE arriving
        __threadfence();                  // publish this CTA's global writes
        if (atomicAdd(&g_barcnt, 1u) == NBLK - 1u) {
            g_barcnt = 0u;
            __threadfence();              // reset visible before release
            g_bargen = gen + 1u;
        } else {
            while (g_bargen == gen) { __nanosleep(64); }
        }
        __threadfence();                  // acquire
    }
    __syncthreads();
}

// ---------------- GEMM: C[m,n] = sum_k A[m,k]*Bw[n,k] + bias1[n] + bias2[n] ----------------
// A: [32768, K] row-major, Bw: [2048, K] row-major, C: [32768, 2048].
// BM=128, BN=64, BK=16, 256 threads, 8x4 register tile per thread.
__global__ __launch_bounds__(256) void gemm_nt_bias(
    const float* __restrict__ A,
    const float* __restrict__ Bw,
    const float* __restrict__ bias1,
    const float* __restrict__ bias2,
    float* __restrict__ C,
    int K)
{
    __shared__ __align__(16) float As[16 * 132];
    __shared__ __align__(16) float Bs[16 * 68];
    const int tid = threadIdx.x;
    const int m0 = blockIdx.y * 128;
    const int n0 = blockIdx.x * 64;
    const int ty = tid >> 4;   // 0..15 -> 8 output rows each
    const int tx = tid & 15;   // 0..15 -> 4 output cols each

    float acc[8][4];
#pragma unroll
    for (int i = 0; i < 8; ++i)
#pragma unroll
        for (int j = 0; j < 4; ++j) acc[i][j] = 0.f;

    for (int k0 = 0; k0 < K; k0 += 16) {
        // stage A tile transposed: As[k][m]
#pragma unroll
        for (int i = 0; i < 2; ++i) {
            int idx = i * 256 + tid;
            int row = idx >> 2, kq = idx & 3;
            float4 v = __ldg((const float4*)&A[(size_t)(m0 + row) * K + k0 + kq * 4]);
            As[(kq * 4 + 0) * 132 + row] = v.x;
            As[(kq * 4 + 1) * 132 + row] = v.y;
            As[(kq * 4 + 2) * 132 + row] = v.z;
            As[(kq * 4 + 3) * 132 + row] = v.w;
        }
        // stage B tile transposed: Bs[k][n]
        {
            int row = tid >> 2, kq = tid & 3;
            float4 v = __ldg((const float4*)&Bw[(size_t)(n0 + row) * K + k0 + kq * 4]);
            Bs[(kq * 4 + 0) * 68 + row] = v.x;
            Bs[(kq * 4 + 1) * 68 + row] = v.y;
            Bs[(kq * 4 + 2) * 68 + row] = v.z;
            Bs[(kq * 4 + 3) * 68 + row] = v.w;
        }
        __syncthreads();
#pragma unroll
        for (int kk = 0; kk < 16; ++kk) {
            float4 a0 = *(const float4*)&As[kk * 132 + ty * 8];
            float4 a1 = *(const float4*)&As[kk * 132 + ty * 8 + 4];
            float4 bv = *(const float4*)&Bs[kk * 68 + tx * 4];
            float a[8] = {a0.x, a0.y, a0.z, a0.w, a1.x, a1.y, a1.z, a1.w};
            float b[4] = {bv.x, bv.y, bv.z, bv.w};
#pragma unroll
            for (int i = 0; i < 8; ++i)
#pragma unroll
                for (int j = 0; j < 4; ++j)
                    acc[i][j] = fmaf(a[i], b[j], acc[i][j]);
        }
        __syncthreads();
    }

    float4 b1 = __ldg((const float4*)&bias1[n0 + tx * 4]);
    float4 b2 = __ldg((const float4*)&bias2[n0 + tx * 4]);
    float bs[4] = {b1.x + b2.x, b1.y + b2.y, b1.z + b2.z, b1.w + b2.w};
#pragma unroll
    for (int i = 0; i < 8; ++i) {
        float4 o = make_float4(acc[i][0] + bs[0], acc[i][1] + bs[1],
                               acc[i][2] + bs[2], acc[i][3] + bs[3]);
        *(float4*)&C[(size_t)(m0 + ty * 8 + i) * G4 + n0 + tx * 4] = o;
    }
}

// ---------------- persistent LSTM recurrence ----------------
// 128 CTAs = 4 batch-tiles (16 b) x 32 unit-tiles (16 u). Each CTA computes the
// 16b x 64c (4 gates x 16 units) gate block each step; W_hh slice lives in smem
// for all 512 steps. One grid barrier per step (double-buffered h).
__global__ __launch_bounds__(256, 1) void lstm_rec(
    const float* __restrict__ Whh,
    const int*   __restrict__ length,
    float*       __restrict__ hs_out,
    int layer)
{
    extern __shared__ float sm[];
    float* sWt   = sm;                    // [512][64]   transposed W slice
    float* sH    = sWt + 512 * 64;        // [16][SHP]   h tile
    float* sRed  = sH + 16 * SHP;         // [4][16][64] k-split partials
    float* sGate = sRed + 4 * 16 * 64;    // [16][68]    finished gates

    const int tid = threadIdx.x;
    const int ui = blockIdx.x & 31, bi = blockIdx.x >> 5;
    const int u0 = ui * 16, b0 = bi * 16;

    // Load W_hh slice transposed: sWt[k*64 + c], local col c = gate*16 + lu.
    for (int i = tid; i < 64 * 128; i += 256) {
        int c = i & 63;
        int kq = i >> 6;  // 0..127
        int grow = (c >> 4) * Hdim + u0 + (c & 15);
        float4 v = __ldg((const float4*)&Whh[(size_t)grow * Hdim + kq * 4]);
        sWt[(kq * 4 + 0) * 64 + c] = v.x;
        sWt[(kq * 4 + 1) * 64 + c] = v.y;
        sWt[(kq * 4 + 2) * 64 + c] = v.z;
        sWt[(kq * 4 + 3) * 64 + c] = v.w;
    }

    // state-cell mapping: one thread per (batch, unit)
    const int ub = tid >> 4, lu = tid & 15;
    const int gb = b0 + ub;
    const int gu = u0 + lu;
    const int len = __ldg(&length[gb]);
    float h0f_r = 0.f, c0f_r = 0.f;
    if (layer) {
        h0f_r = g_h0f[gb * Hdim + gu];
        c0f_r = g_c0f[gb * Hdim + gu];
    }
    float h_reg = 0.f, c_reg = 0.f;
    g_bufA[gb * Hdim + gu] = 0.f;   // h(t=-1) = 0

    // dot-phase mapping: tid = ks*64 + bq*16 + cq
    const int ks = tid >> 6;          // K split 0..3 (128 k each)
    const int bq = (tid >> 4) & 3;    // 4 batch rows
    const int cq = tid & 15;          // 4 gate cols
    const int kbeg = ks * 128;
    const int rb0 = (bq * 4 + 0) * SHP;
    const int rb1 = (bq * 4 + 1) * SHP;
    const int rb2 = (bq * 4 + 2) * SHP;
    const int rb3 = (bq * 4 + 3) * SHP;

    // combine mapping: batch row ub, cols c0c..c0c+3 (one gate, 4 units)
    const int c0c = (tid & 15) * 4;
    const size_t Goff_c = (size_t)(c0c >> 4) * Hdim + u0 + (c0c & 15);

    grid_barrier();   // publish h(t=-1)=0 chip-wide

    for (int t = 0; t < Tdim; ++t) {
        const float* hrd = (t & 1) ? g_bufB : g_bufA;
        float*       hwr = (t & 1) ? g_bufA : g_bufB;

        // stage h tile (L2-coherent reads)
        for (int i = tid; i < 16 * 128; i += 256) {
            int bb = i >> 7, kq = i & 127;
            float4 v = __ldcg((const float4*)&hrd[(b0 + bb) * Hdim + kq * 4]);
            *(float4*)&sH[bb * SHP + kq * 4] = v;
        }
        __syncthreads();

        // dot: acc[4b][4c] over this thread's 128 k
        float acc[4][4];
#pragma unroll
        for (int i = 0; i < 4; ++i)
#pragma unroll
            for (int j = 0; j < 4; ++j) acc[i][j] = 0.f;

#pragma unroll 4
        for (int k = kbeg; k < kbeg + 128; ++k) {
            float4 w = *(const float4*)&sWt[(k << 6) + (cq << 2)];
            float h0 = sH[rb0 + k];
            float h1 = sH[rb1 + k];
            float h2 = sH[rb2 + k];
            float h3 = sH[rb3 + k];
            acc[0][0] = fmaf(h0, w.x, acc[0][0]); acc[0][1] = fmaf(h0, w.y, acc[0][1]);
            acc[0][2] = fmaf(h0, w.z, acc[0][2]); acc[0][3] = fmaf(h0, w.w, acc[0][3]);
            acc[1][0] = fmaf(h1, w.x, acc[1][0]); acc[1][1] = fmaf(h1, w.y, acc[1][1]);
            acc[1][2] = fmaf(h1, w.z, acc[1][2]); acc[1][3] = fmaf(h1, w.w, acc[1][3]);
            acc[2][0] = fmaf(h2, w.x, acc[2][0]); acc[2][1] = fmaf(h2, w.y, acc[2][1]);
            acc[2][2] = fmaf(h2, w.z, acc[2][2]); acc[2][3] = fmaf(h2, w.w, acc[2][3]);
            acc[3][0] = fmaf(h3, w.x, acc[3][0]); acc[3][1] = fmaf(h3, w.y, acc[3][1]);
            acc[3][2] = fmaf(h3, w.z, acc[3][2]); acc[3][3] = fmaf(h3, w.w, acc[3][3]);
        }
#pragma unroll
        for (int i = 0; i < 4; ++i) {
            *(float4*)&sRed[ks * 1024 + (bq * 4 + i) * 64 + cq * 4] =
                make_float4(acc[i][0], acc[i][1], acc[i][2], acc[i][3]);
        }
        __syncthreads();

        // combine k-split partials + precomputed input gates
        {
            float4 s0 = *(const float4*)&sRed[0 * 1024 + ub * 64 + c0c];
            float4 s1 = *(const float4*)&sRed[1 * 1024 + ub * 64 + c0c];
            float4 s2 = *(const float4*)&sRed[2 * 1024 + ub * 64 + c0c];
            float4 s3 = *(const float4*)&sRed[3 * 1024 + ub * 64 + c0c];
            float4 Gv = __ldg((const float4*)&g_G[((size_t)gb * Tdim + t) * G4 + Goff_c]);
            float4 o;
            o.x = s0.x + s1.x + s2.x + s3.x + Gv.x;
            o.y = s0.y + s1.y + s2.y + s3.y + Gv.y;
            o.z = s0.z + s1.z + s2.z + s3.z + Gv.z;
            o.w = s0.w + s1.w + s2.w + s3.w + Gv.w;
            *(float4*)&sGate[ub * 68 + c0c] = o;
        }
        __syncthreads();

        // state update (i,f,g,o ordering per jnp.split)
        {
            float gi = sGate[ub * 68 + 0  + lu];
            float gf = sGate[ub * 68 + 16 + lu];
            float gg = sGate[ub * 68 + 32 + lu];
            float go = sGate[ub * 68 + 48 + lu];
            float si = 1.f / (1.f + expf(-gi));
            float sf = 1.f / (1.f + expf(-gf));
            float so = 1.f / (1.f + expf(-go));
            float cn = sf * c_reg + si * tanhf(gg);
            float hn = so * tanhf(cn);
            if (t < len) {
                c_reg = cn; h_reg = hn;
            } else if (layer) {
                c_reg = c0f_r; h_reg = h0f_r;   // layer-1 masked: reset to layer-0 final
            }                                    // layer-0 masked: carry (keep regs)
            hwr[gb * Hdim + gu] = h_reg;
            hs_out[((size_t)gb * Tdim + t) * Hdim + gu] = h_reg;
        }

        grid_barrier();
    }

    if (layer == 0) {
        g_h0f[gb * Hdim + gu] = h_reg;
        g_c0f[gb * Hdim + gu] = c_reg;
    }
}

// ---------------- tail: out2 = hs1[b=63] ----------------
__global__ void tail_copy(float* __restrict__ out) {
    size_t i = (size_t)blockIdx.x * 256 + threadIdx.x;   // 65536 float4s
    float4 v = *(const float4*)&out[(size_t)63 * Tdim * Hdim + i * 4];
    *(float4*)&out[(size_t)Bdim * Tdim * Hdim + i * 4] = v;
}

// ---------------- launch ----------------
extern "C" void kernel_launch(void* const* d_in, const int* in_sizes, int n_in,
                              void* d_out, int out_size) {
    const float* x    = (const float*)d_in[0];
    const int*   len  = (const int*)  d_in[1];
    const float* Wih0 = (const float*)d_in[2];
    const float* Whh0 = (const float*)d_in[3];
    const float* bih0 = (const float*)d_in[4];
    const float* bhh0 = (const float*)d_in[5];
    const float* Wih1 = (const float*)d_in[6];
    const float* Whh1 = (const float*)d_in[7];
    const float* bih1 = (const float*)d_in[8];
    const float* bhh1 = (const float*)d_in[9];
    float* out = (float*)d_out;

    constexpr size_t REC_SMEM =
        (512 * 64 + 16 * SHP + 4 * 16 * 64 + 16 * 68) * sizeof(float);  // 184832 B
    cudaFuncSetAttribute(lstm_rec, cudaFuncAttributeMaxDynamicSharedMemorySize,
                         (int)REC_SMEM);

    void* pG = nullptr;  cudaGetSymbolAddress(&pG,  g_G);
    void* pH0 = nullptr; cudaGetSymbolAddress(&pH0, g_hs0);

    dim3 gemm_grid(G4 / 64, (Bdim * Tdim) / 128);   // (32, 256)

    // Layer 0: input projection then recurrence
    gemm_nt_bias<<<gemm_grid, 256>>>(x, Wih0, bih0, bhh0, (float*)pG, INdim);
    lstm_rec<<<NBLK, 256, REC_SMEM>>>(Whh0, len, (float*)pH0, 0);

    // Layer 1: input projection (from hs0) then recurrence, writes hs1 to out
    gemm_nt_bias<<<gemm_grid, 256>>>((const float*)pH0, Wih1, bih1, bhh1,
                                     (float*)pG, Hdim);
    lstm_rec<<<NBLK, 256, REC_SMEM>>>(Whh1, len, out, 1);

    // output tail = hs1[last batch]
    tail_copy<<<256, 256>>>(out);
}